// round 7
// baseline (speedup 1.0000x reference)
#include <cuda_runtime.h>
#include <math.h>
#include <stdint.h>

// ---------------------------------------------------------------------------
// Shapes
// ---------------------------------------------------------------------------
#define BATCH  8192
#define DIN    4096
#define DMODEL 512
#define FDIM   2048
#define NH     3
#define HD     256
#define OUTD   896

// big GEMM tile (128x256, 8 warps of 64x64), 3-stage pipeline, 1 CTA/SM
#define BM 128
#define BN 256
#define BK 32
#define THREADS 256
#define AST 36
#define A_STAGE (BM * AST)                 // 4608 floats
#define B_STAGE (4 * BN * 8)               // 8192 floats  [g][n][8]
#define STAGE (A_STAGE + B_STAGE)          // 12800 floats
#define SMB_BIG (3 * STAGE * 4)            // 153600 B

// small GEMM tile (128x128, 8 warps of 32x64), 2-stage, 2 CTA/SM
#define SBN 128
#define SB_STAGE (4 * SBN * 8)             // 4096 floats
#define SSTAGE (A_STAGE + SB_STAGE)        // 8704 floats
#define SMB_SM (2 * SSTAGE * 4)            // 69632 B

// Epilogue flags
#define F_B2   1
#define F_GELU 2
#define F_RES  4

// ---------------------------------------------------------------------------
// Scratch
// ---------------------------------------------------------------------------
__device__ float g_h  [BATCH * DMODEL];
__device__ float g_t  [BATCH * DMODEL];
__device__ float g_cat[BATCH * 2 * DMODEL];
__device__ float g_ff [BATCH * FDIM];
__device__ float g_z  [BATCH * NH * HD];

// tf32-rounded, pair-packed weights: [K/8][N][8], pairs (k,k+4) adjacent
__device__ float g_wp_in [DIN * DMODEL];
__device__ float g_wp_osa[DMODEL * DMODEL];
__device__ float g_wp_oca[DMODEL * DMODEL];
__device__ float g_wp_stk[2 * DMODEL * DMODEL];   // stacked [Wsc ; Wcc], K=1024
__device__ float g_wp_ff1[DMODEL * FDIM];
__device__ float g_wp_ff2[FDIM * DMODEL];
__device__ float g_wp_h1 [NH * DMODEL * HD];
__device__ float g_wp_h2 [NH * HD * OUTD];

__device__ float g_tmp1[DMODEL * DMODEL];
__device__ float g_tmp2[DMODEL * DMODEL];
__device__ float g_bstk[DMODEL];
__device__ float g_zero[1024];

// ---------------------------------------------------------------------------
// Helpers
// ---------------------------------------------------------------------------
static __device__ __forceinline__ void cp16(float* sm, const float* gm) {
    unsigned s = (unsigned)__cvta_generic_to_shared(sm);
    asm volatile("cp.async.ca.shared.global [%0], [%1], 16;\n" :: "r"(s), "l"(gm));
}
static __device__ __forceinline__ unsigned f2tf32(float f) {
    unsigned u;
    asm("cvt.rna.tf32.f32 %0, %1;" : "=r"(u) : "f"(f));
    return u;
}
static __device__ __forceinline__ float gelu_exact(float v) {
    return 0.5f * v * (1.0f + erff(v * 0.70710678118654752f));
}
#define MMA_TF32(acc, a0, a1, a2, a3, b0, b1)                                  \
    asm volatile(                                                              \
        "mma.sync.aligned.m16n8k8.row.col.f32.tf32.tf32.f32 "                  \
        "{%0,%1,%2,%3},{%4,%5,%6,%7},{%8,%9},{%0,%1,%2,%3};\n"                 \
        : "+f"((acc)[0]), "+f"((acc)[1]), "+f"((acc)[2]), "+f"((acc)[3])       \
        : "r"(a0), "r"(a1), "r"(a2), "r"(a3), "r"(b0), "r"(b1))

// ---------------------------------------------------------------------------
// BIG: 128x256 CTA tile, 8 warps (2 M x 4 N) of 64x64, 3-stage pipeline.
// ---------------------------------------------------------------------------
template<int FLAGS>
__global__ void __launch_bounds__(THREADS, 1) gemm_big(
    const float* __restrict__ A, int lda, long sA,
    const float* __restrict__ B, int ldbN, long sB,
    float* __restrict__ C, int ldc, long sC,
    int K,
    const float* __restrict__ bias, int sBias,
    const float* __restrict__ bias2,
    const float* __restrict__ res)
{
    extern __shared__ float sm[];
    const int tid  = threadIdx.x;
    const int lane = tid & 31;
    const int warp = tid >> 5;
    const int wm = warp & 1;
    const int wn = warp >> 1;
    const int q  = lane >> 2, cc = lane & 3;

    const int z = blockIdx.z;
    A    += (long)z * sA;
    B    += (long)z * sB;
    C    += (long)z * sC;
    bias += (long)z * sBias;
    const float* resb = (FLAGS & F_RES) ? (res + (long)z * sC) : nullptr;

    const long mBase = (long)blockIdx.y * BM;
    const int  nBase = blockIdx.x * BN;
    const float* Ag = A + mBase * lda;

    const int numK = K / BK;

    float4 fA[4];
    auto ldgA = [&](int kt) {
#pragma unroll
        for (int i = 0; i < 4; i++) {
            int f = i * THREADS + tid;
            int r = f >> 3, c = (f & 7) * 4;
            fA[i] = *(const float4*)(Ag + (long)r * lda + kt * BK + c);
        }
    };
    auto stsA = [&](int stg) {
        float* As = sm + stg * STAGE;
#pragma unroll
        for (int i = 0; i < 4; i++) {
            int f = i * THREADS + tid;
            int r = f >> 3, c = (f & 7) * 4;
            float4 v = fA[i];
            *(uint4*)(As + r * AST + c) =
                make_uint4(f2tf32(v.x), f2tf32(v.y), f2tf32(v.z), f2tf32(v.w));
        }
    };
    auto cpB = [&](int kt, int stg) {
        float* Bs = sm + stg * STAGE + A_STAGE;
#pragma unroll
        for (int i = 0; i < 8; i++) {
            int idx = i * THREADS + tid;
            int half = idx & 1;
            int n = (idx >> 1) & 255;
            int g = idx >> 9;
            const float* src = B + ((long)(kt * 4 + g) * ldbN + nBase + n) * 8 + half * 4;
            cp16(Bs + (g * BN + n) * 8 + half * 4, src);
        }
    };

    float acc[4][8][4];
#pragma unroll
    for (int a = 0; a < 4; a++)
#pragma unroll
        for (int b = 0; b < 8; b++)
#pragma unroll
            for (int c = 0; c < 4; c++) acc[a][b][c] = 0.f;

    // ---- prologue ----
    ldgA(0); stsA(0);
    cpB(0, 0);
    asm volatile("cp.async.commit_group;\n" ::: "memory");
    ldgA(1);
    cpB(1, 1);
    asm volatile("cp.async.commit_group;\n" ::: "memory");

    for (int kt = 0; kt < numK; kt++) {
        asm volatile("cp.async.wait_group 1;\n" ::: "memory");
        __syncthreads();

        if (kt + 1 < numK) stsA((kt + 1) % 3);
        if (kt + 2 < numK) { ldgA(kt + 2); cpB(kt + 2, (kt + 2) % 3); }
        asm volatile("cp.async.commit_group;\n" ::: "memory");

        const float* As = sm + (kt % 3) * STAGE + (wm * 64) * AST;
        const float* Bs = sm + (kt % 3) * STAGE + A_STAGE;

#pragma unroll
        for (int ks = 0; ks < 4; ks++) {
            uint32_t af[4][4];
#pragma unroll
            for (int mi = 0; mi < 4; mi++) {
                const float* ap = As + (mi * 16 + q) * AST + ks * 8 + cc;
                af[mi][0] = __float_as_uint(ap[0]);
                af[mi][1] = __float_as_uint(ap[8 * AST]);
                af[mi][2] = __float_as_uint(ap[4]);
                af[mi][3] = __float_as_uint(ap[8 * AST + 4]);
            }
            uint32_t bf[8][2];
#pragma unroll
            for (int ni = 0; ni < 8; ni++) {
                uint2 bv = *(const uint2*)(Bs + ((ks * BN + wn * 64 + ni * 8 + q) * 8 + cc * 2));
                bf[ni][0] = bv.x; bf[ni][1] = bv.y;
            }
#pragma unroll
            for (int mi = 0; mi < 4; mi++)
#pragma unroll
                for (int ni = 0; ni < 8; ni++)
                    MMA_TF32(acc[mi][ni], af[mi][0], af[mi][1], af[mi][2], af[mi][3],
                             bf[ni][0], bf[ni][1]);
        }
    }

    // ---- fused epilogue ----
    const int rBase = (int)mBase + wm * 64;
    const int cBase = nBase + wn * 64;
#pragma unroll
    for (int mi = 0; mi < 4; mi++) {
#pragma unroll
        for (int ni = 0; ni < 8; ni++) {
            int c = cBase + ni * 8 + cc * 2;
            float b0 = bias[c], b1 = bias[c + 1];
            if (FLAGS & F_B2) { b0 += bias2[c]; b1 += bias2[c + 1]; }
#pragma unroll
            for (int h = 0; h < 2; h++) {
                long row = rBase + mi * 16 + q + 8 * h;
                float v0 = acc[mi][ni][2 * h + 0] + b0;
                float v1 = acc[mi][ni][2 * h + 1] + b1;
                if (FLAGS & F_GELU) { v0 = gelu_exact(v0); v1 = gelu_exact(v1); }
                long idx = row * ldc + c;
                if (FLAGS & F_RES) {
                    float2 rr = *(const float2*)(resb + idx);
                    v0 += rr.x; v1 += rr.y;
                }
                *(float2*)(C + idx) = make_float2(v0, v1);
            }
        }
    }
}

// ---------------------------------------------------------------------------
// SMALL: 128x128 CTA tile, 8 warps (4 M x 2 N) of 32x64, 2-stage, 2 CTA/SM.
// (R5-proven configuration.)
// ---------------------------------------------------------------------------
template<int FLAGS>
__global__ void __launch_bounds__(THREADS, 2) gemm_sm(
    const float* __restrict__ A, int lda, long sA,
    const float* __restrict__ B, int ldbN, long sB,
    float* __restrict__ C, int ldc, long sC,
    int K,
    const float* __restrict__ bias, int sBias)
{
    extern __shared__ float sm[];
    const int tid  = threadIdx.x;
    const int lane = tid & 31;
    const int warp = tid >> 5;
    const int wm = warp & 3;
    const int wn = warp >> 2;
    const int q  = lane >> 2, cc = lane & 3;

    const int z = blockIdx.z;
    A    += (long)z * sA;
    B    += (long)z * sB;
    C    += (long)z * sC;
    bias += (long)z * sBias;

    const long mBase = (long)blockIdx.y * BM;
    const int  nBase = blockIdx.x * SBN;
    const float* Ag = A + mBase * lda;

    const int numK = K / BK;

    float4 fA[4];
    auto ldgA = [&](int kt) {
#pragma unroll
        for (int i = 0; i < 4; i++) {
            int f = i * THREADS + tid;
            int r = f >> 3, c = (f & 7) * 4;
            fA[i] = *(const float4*)(Ag + (long)r * lda + kt * BK + c);
        }
    };
    auto stsA = [&](int buf) {
        float* As = sm + buf * SSTAGE;
#pragma unroll
        for (int i = 0; i < 4; i++) {
            int f = i * THREADS + tid;
            int r = f >> 3, c = (f & 7) * 4;
            float4 v = fA[i];
            *(uint4*)(As + r * AST + c) =
                make_uint4(f2tf32(v.x), f2tf32(v.y), f2tf32(v.z), f2tf32(v.w));
        }
    };
    auto cpB = [&](int kt, int buf) {
        float* Bs = sm + buf * SSTAGE + A_STAGE;
#pragma unroll
        for (int i = 0; i < 4; i++) {
            int idx = i * THREADS + tid;
            int half = idx & 1;
            int n = (idx >> 1) & 127;
            int g = idx >> 8;
            const float* src = B + ((long)(kt * 4 + g) * ldbN + nBase + n) * 8 + half * 4;
            cp16(Bs + (g * SBN + n) * 8 + half * 4, src);
        }
    };

    float acc[2][8][4];
#pragma unroll
    for (int a = 0; a < 2; a++)
#pragma unroll
        for (int b = 0; b < 8; b++)
#pragma unroll
            for (int c = 0; c < 4; c++) acc[a][b][c] = 0.f;

    ldgA(0); stsA(0); cpB(0, 0);
    asm volatile("cp.async.commit_group;\n" ::: "memory");

    for (int kt = 0; kt < numK; kt++) {
        asm volatile("cp.async.wait_group 0;\n" ::: "memory");
        __syncthreads();

        if (kt + 1 < numK) {
            ldgA(kt + 1);
            cpB(kt + 1, (kt + 1) & 1);
            asm volatile("cp.async.commit_group;\n" ::: "memory");
        }

        const float* As = sm + (kt & 1) * SSTAGE + (wm * 32) * AST;
        const float* Bs = sm + (kt & 1) * SSTAGE + A_STAGE;

#pragma unroll
        for (int ks = 0; ks < 4; ks++) {
            uint32_t af[2][4];
#pragma unroll
            for (int mi = 0; mi < 2; mi++) {
                const float* ap = As + (mi * 16 + q) * AST + ks * 8 + cc;
                af[mi][0] = __float_as_uint(ap[0]);
                af[mi][1] = __float_as_uint(ap[8 * AST]);
                af[mi][2] = __float_as_uint(ap[4]);
                af[mi][3] = __float_as_uint(ap[8 * AST + 4]);
            }
            uint32_t bf[8][2];
#pragma unroll
            for (int ni = 0; ni < 8; ni++) {
                uint2 bv = *(const uint2*)(Bs + ((ks * SBN + wn * 64 + ni * 8 + q) * 8 + cc * 2));
                bf[ni][0] = bv.x; bf[ni][1] = bv.y;
            }
#pragma unroll
            for (int mi = 0; mi < 2; mi++)
#pragma unroll
                for (int ni = 0; ni < 8; ni++)
                    MMA_TF32(acc[mi][ni], af[mi][0], af[mi][1], af[mi][2], af[mi][3],
                             bf[ni][0], bf[ni][1]);
        }

        if (kt + 1 < numK) stsA((kt + 1) & 1);
    }

    const int rBase = (int)mBase + wm * 32;
    const int cBase = nBase + wn * 64;
#pragma unroll
    for (int mi = 0; mi < 2; mi++) {
#pragma unroll
        for (int ni = 0; ni < 8; ni++) {
            int c = cBase + ni * 8 + cc * 2;
            float b0 = bias[c], b1 = bias[c + 1];
#pragma unroll
            for (int h = 0; h < 2; h++) {
                long row = rBase + mi * 16 + q + 8 * h;
                float v0 = acc[mi][ni][2 * h + 0] + b0;
                float v1 = acc[mi][ni][2 * h + 1] + b1;
                if (FLAGS & F_GELU) { v0 = gelu_exact(v0); v1 = gelu_exact(v1); }
                long idx = row * ldc + c;
                *(float2*)(C + idx) = make_float2(v0, v1);
            }
        }
    }
}

// ---------------------------------------------------------------------------
// Weight pack: [K,N] fp32 -> [K/8][N][8] tf32, pair order {k0,k4,k1,k5,k2,k6,k3,k7}
// ---------------------------------------------------------------------------
__global__ void pack_kernel(const float* __restrict__ in, float* __restrict__ out,
                            int K, int N)
{
    const long zo = (long)blockIdx.z * K * N;
    const int n = blockIdx.x * 128 + threadIdx.x;
    const int g = blockIdx.y;
    float v[8];
#pragma unroll
    for (int k = 0; k < 8; k++)
        v[k] = in[zo + (long)(g * 8 + k) * N + n];
    float* o = out + zo + ((long)g * N + n) * 8;
    *(uint4*)(o)     = make_uint4(f2tf32(v[0]), f2tf32(v[4]), f2tf32(v[1]), f2tf32(v[5]));
    *(uint4*)(o + 4) = make_uint4(f2tf32(v[2]), f2tf32(v[6]), f2tf32(v[3]), f2tf32(v[7]));
}

// ---------------------------------------------------------------------------
// prep_bias: zero init + bstk[n] = bosa+boca + bvsa@Wosa + bvca@Woca.
// 4 independent accumulators to break the FMA chain; coalesced over n.
// grid 4 x 128 threads.
// ---------------------------------------------------------------------------
__global__ void prep_bias(const float* __restrict__ bv_sa, const float* __restrict__ wo_sa,
                          const float* __restrict__ bo_sa,
                          const float* __restrict__ bv_ca, const float* __restrict__ wo_ca,
                          const float* __restrict__ bo_ca,
                          float* __restrict__ bstk, float* __restrict__ zero)
{
    const int n = blockIdx.x * 128 + threadIdx.x;
    zero[n] = 0.f;
    zero[n + 512] = 0.f;
    float a0 = 0.f, a1 = 0.f, a2 = 0.f, a3 = 0.f;
#pragma unroll 4
    for (int k = 0; k < DMODEL; k += 4) {
        a0 += bv_sa[k+0] * wo_sa[(k+0) * DMODEL + n] + bv_ca[k+0] * wo_ca[(k+0) * DMODEL + n];
        a1 += bv_sa[k+1] * wo_sa[(k+1) * DMODEL + n] + bv_ca[k+1] * wo_ca[(k+1) * DMODEL + n];
        a2 += bv_sa[k+2] * wo_sa[(k+2) * DMODEL + n] + bv_ca[k+2] * wo_ca[(k+2) * DMODEL + n];
        a3 += bv_sa[k+3] * wo_sa[(k+3) * DMODEL + n] + bv_ca[k+3] * wo_ca[(k+3) * DMODEL + n];
    }
    bstk[n] = (a0 + a1) + (a2 + a3) + bo_sa[n] + bo_ca[n];
}

// ---------------------------------------------------------------------------
// Row LayerNorm (float4, 128 threads)
// ---------------------------------------------------------------------------
__global__ void ln_kernel(const float* __restrict__ in, float* __restrict__ out,
                          const float* __restrict__ g, const float* __restrict__ b,
                          int C, int headMod)
{
    __shared__ float red[8];
    const int row = blockIdx.x;
    const float* x = in + (long)row * C;
    float* y = out + (long)row * C;
    const int go = headMod ? (row % headMod) * C : 0;

    float s = 0.f, s2 = 0.f;
    for (int i = threadIdx.x * 4; i < C; i += 512) {
        float4 v = *(const float4*)(x + i);
        s  += v.x + v.y + v.z + v.w;
        s2 += v.x * v.x + v.y * v.y + v.z * v.z + v.w * v.w;
    }
#pragma unroll
    for (int o = 16; o; o >>= 1) {
        s  += __shfl_xor_sync(0xffffffffu, s, o);
        s2 += __shfl_xor_sync(0xffffffffu, s2, o);
    }
    const int w = threadIdx.x >> 5;
    if ((threadIdx.x & 31) == 0) { red[w] = s; red[4 + w] = s2; }
    __syncthreads();
    if (threadIdx.x == 0) {
        float ts = 0.f, ts2 = 0.f;
#pragma unroll
        for (int i = 0; i < 4; i++) { ts += red[i]; ts2 += red[4 + i]; }
        red[0] = ts; red[4] = ts2;
    }
    __syncthreads();
    const float mean = red[0] / C;
    const float var  = red[4] / C - mean * mean;
    const float inv  = rsqrtf(var + 1e-5f);
    for (int i = threadIdx.x * 4; i < C; i += 512) {
        float4 v  = *(const float4*)(x + i);
        float4 gg = *(const float4*)(g + go + i);
        float4 bb = *(const float4*)(b + go + i);
        float4 o;
        o.x = (v.x - mean) * inv * gg.x + bb.x;
        o.y = (v.y - mean) * inv * gg.y + bb.y;
        o.z = (v.z - mean) * inv * gg.z + bb.z;
        o.w = (v.w - mean) * inv * gg.w + bb.w;
        *(float4*)(y + i) = o;
    }
}

// ---------------------------------------------------------------------------
// lncat: cat[row, 0:512] = ln1(h[row]); cat[row, 512:1024] = h[row]
// 128 threads, one float4 each.
// ---------------------------------------------------------------------------
__global__ void lncat_kernel(const float* __restrict__ in, float* __restrict__ cat,
                             const float* __restrict__ g, const float* __restrict__ b)
{
    __shared__ float red[8];
    const int row = blockIdx.x;
    const float* x = in + (long)row * DMODEL;
    float* y = cat + (long)row * (2 * DMODEL);
    const int i = threadIdx.x * 4;

    float4 v = *(const float4*)(x + i);
    float s  = v.x + v.y + v.z + v.w;
    float s2 = v.x * v.x + v.y * v.y + v.z * v.z + v.w * v.w;
#pragma unroll
    for (int o = 16; o; o >>= 1) {
        s  += __shfl_xor_sync(0xffffffffu, s, o);
        s2 += __shfl_xor_sync(0xffffffffu, s2, o);
    }
    const int w = threadIdx.x >> 5;
    if ((threadIdx.x & 31) == 0) { red[w] = s; red[4 + w] = s2; }
    __syncthreads();
    if (threadIdx.x == 0) {
        float ts = 0.f, ts2 = 0.f;
#pragma unroll
        for (int j = 0; j < 4; j++) { ts += red[j]; ts2 += red[4 + j]; }
        red[0] = ts; red[4] = ts2;
    }
    __syncthreads();
    const float mean = red[0] / DMODEL;
    const float var  = red[4] / DMODEL - mean * mean;
    const float inv  = rsqrtf(var + 1e-5f);
    float4 gg = *(const float4*)(g + i);
    float4 bb = *(const float4*)(b + i);
    float4 o;
    o.x = (v.x - mean) * inv * gg.x + bb.x;
    o.y = (v.y - mean) * inv * gg.y + bb.y;
    o.z = (v.z - mean) * inv * gg.z + bb.z;
    o.w = (v.w - mean) * inv * gg.w + bb.w;
    *(float4*)(y + i) = o;
    *(float4*)(y + DMODEL + i) = v;
}

// ---------------------------------------------------------------------------
// Launch
// ---------------------------------------------------------------------------
extern "C" void kernel_launch(void* const* d_in, const int* in_sizes, int n_in,
                              void* d_out, int out_size)
{
    const float* x      = (const float*)d_in[0];
    const float* w_in   = (const float*)d_in[1];
    const float* b_in   = (const float*)d_in[2];
    const float* pos    = (const float*)d_in[3];
    const float* ln1_g  = (const float*)d_in[4];
    const float* ln1_b  = (const float*)d_in[5];
    const float* wv_sa  = (const float*)d_in[6];
    const float* bv_sa  = (const float*)d_in[7];
    const float* wo_sa  = (const float*)d_in[8];
    const float* bo_sa  = (const float*)d_in[9];
    const float* wv_ca  = (const float*)d_in[12];
    const float* bv_ca  = (const float*)d_in[13];
    const float* wo_ca  = (const float*)d_in[14];
    const float* bo_ca  = (const float*)d_in[15];
    const float* ln3_g  = (const float*)d_in[16];
    const float* ln3_b  = (const float*)d_in[17];
    const float* w_ff1  = (const float*)d_in[18];
    const float* b_ff1  = (const float*)d_in[19];
    const float* w_ff2  = (const float*)d_in[20];
    const float* b_ff2  = (const float*)d_in[21];
    const float* lnout_g= (const float*)d_in[22];
    const float* lnout_b= (const float*)d_in[23];
    const float* wh1    = (const float*)d_in[24];
    const float* bh1    = (const float*)d_in[25];
    const float* lnh_g  = (const float*)d_in[26];
    const float* lnh_b  = (const float*)d_in[27];
    const float* wh2    = (const float*)d_in[28];
    const float* bh2    = (const float*)d_in[29];
    float* out = (float*)d_out;

    float *h, *t, *cat, *ff, *zz, *tmp1, *tmp2, *bstk, *zero;
    float *wp_in, *wp_osa, *wp_oca, *wp_stk, *wp_ff1, *wp_ff2, *wp_h1, *wp_h2;
    cudaGetSymbolAddress((void**)&h,    g_h);
    cudaGetSymbolAddress((void**)&t,    g_t);
    cudaGetSymbolAddress((void**)&cat,  g_cat);
    cudaGetSymbolAddress((void**)&ff,   g_ff);
    cudaGetSymbolAddress((void**)&zz,   g_z);
    cudaGetSymbolAddress((void**)&tmp1, g_tmp1);
    cudaGetSymbolAddress((void**)&tmp2, g_tmp2);
    cudaGetSymbolAddress((void**)&bstk, g_bstk);
    cudaGetSymbolAddress((void**)&zero, g_zero);
    cudaGetSymbolAddress((void**)&wp_in,  g_wp_in);
    cudaGetSymbolAddress((void**)&wp_osa, g_wp_osa);
    cudaGetSymbolAddress((void**)&wp_oca, g_wp_oca);
    cudaGetSymbolAddress((void**)&wp_stk, g_wp_stk);
    cudaGetSymbolAddress((void**)&wp_ff1, g_wp_ff1);
    cudaGetSymbolAddress((void**)&wp_ff2, g_wp_ff2);
    cudaGetSymbolAddress((void**)&wp_h1,  g_wp_h1);
    cudaGetSymbolAddress((void**)&wp_h2,  g_wp_h2);

    cudaFuncSetAttribute(gemm_big<F_B2>,   cudaFuncAttributeMaxDynamicSharedMemorySize, SMB_BIG);
    cudaFuncSetAttribute(gemm_big<F_RES>,  cudaFuncAttributeMaxDynamicSharedMemorySize, SMB_BIG);
    cudaFuncSetAttribute(gemm_big<F_GELU>, cudaFuncAttributeMaxDynamicSharedMemorySize, SMB_BIG);
    cudaFuncSetAttribute(gemm_sm<0>,       cudaFuncAttributeMaxDynamicSharedMemorySize, SMB_SM);

    dim3 blk(THREADS);
    const int MG = BATCH / BM;  // 64

    // ---- launch order arranged so launch index 5 = gemm1 (ncu -s 5 -c 1) ----
    // [0] pack w_in
    pack_kernel<<<dim3(DMODEL / 128, DIN / 8, 1), 128>>>(w_in, wp_in, DIN, DMODEL);
    // [1] pack wo_sa
    pack_kernel<<<dim3(DMODEL / 128, DMODEL / 8, 1), 128>>>(wo_sa, wp_osa, DMODEL, DMODEL);
    // [2] pack wo_ca
    pack_kernel<<<dim3(DMODEL / 128, DMODEL / 8, 1), 128>>>(wo_ca, wp_oca, DMODEL, DMODEL);
    // [3] bias fold + zero init (needed by fold GEMMs)
    prep_bias<<<4, 128>>>(bv_sa, wo_sa, bo_sa, bv_ca, wo_ca, bo_ca, bstk, zero);
    // [4] fold1: tmp1 = Wvsa @ Wosa
    gemm_sm<0><<<dim3(DMODEL / SBN, DMODEL / BM, 1), blk, SMB_SM>>>(
        wv_sa, DMODEL, 0, wp_osa, DMODEL, 0, tmp1, DMODEL, 0, DMODEL, zero, 0);
    // [5] gemm1: h = x @ w_in + b_in + pos         <-- PROFILED LAUNCH
    gemm_big<F_B2><<<dim3(DMODEL / BN, MG, 1), blk, SMB_BIG>>>(
        x, DIN, 0, wp_in, DMODEL, 0, h, DMODEL, 0, DIN, b_in, 0, pos, nullptr);
    // [6] fold2: tmp2 = Wvca @ Woca
    gemm_sm<0><<<dim3(DMODEL / SBN, DMODEL / BM, 1), blk, SMB_SM>>>(
        wv_ca, DMODEL, 0, wp_oca, DMODEL, 0, tmp2, DMODEL, 0, DMODEL, zero, 0);
    // [7,8] stack folds into wp_stk (packed K=1024)
    pack_kernel<<<dim3(DMODEL / 128, DMODEL / 8, 1), 128>>>(tmp1, wp_stk, DMODEL, DMODEL);
    pack_kernel<<<dim3(DMODEL / 128, DMODEL / 8, 1), 128>>>(
        tmp2, wp_stk + (DMODEL / 8) * DMODEL * 8, DMODEL, DMODEL);
    // [9..12] remaining weight packs
    pack_kernel<<<dim3(FDIM / 128, DMODEL / 8, 1), 128>>>(w_ff1, wp_ff1, DMODEL, FDIM);
    pack_kernel<<<dim3(DMODEL / 128, FDIM / 8, 1), 128>>>(w_ff2, wp_ff2, FDIM, DMODEL);
    pack_kernel<<<dim3(HD / 128, DMODEL / 8, NH), 128>>>(wh1, wp_h1, DMODEL, HD);
    pack_kernel<<<dim3(OUTD / 128, HD / 8, NH), 128>>>(wh2, wp_h2, HD, OUTD);

    // [13] cat = [ln1(h) | h]
    lncat_kernel<<<BATCH, 128>>>(h, cat, ln1_g, ln1_b);

    // [14] h = h + cat @ Wstk + bstk     (folded self-attn + cross-attn, K=1024)
    gemm_big<F_RES><<<dim3(DMODEL / BN, MG, 1), blk, SMB_BIG>>>(
        cat, 2 * DMODEL, 0, wp_stk, DMODEL, 0, h, DMODEL, 0, 2 * DMODEL,
        bstk, 0, nullptr, h);

    // [15] t = ln3(h)
    ln_kernel<<<BATCH, 128>>>(h, t, ln3_g, ln3_b, DMODEL, 0);

    // [16] ff = gelu(t @ w_ff1 + b_ff1)
    gemm_big<F_GELU><<<dim3(FDIM / BN, MG, 1), blk, SMB_BIG>>>(
        t, DMODEL, 0, wp_ff1, FDIM, 0, ff, FDIM, 0, DMODEL, b_ff1, 0, nullptr, nullptr);

    // [17] h = h + ff @ w_ff2 + b_ff2   (in place)
    gemm_big<F_RES><<<dim3(DMODEL / BN, MG, 1), blk, SMB_BIG>>>(
        ff, FDIM, 0, wp_ff2, DMODEL, 0, h, DMODEL, 0, FDIM, b_ff2, 0, nullptr, h);

    // [18] t = lnout(h)
    ln_kernel<<<BATCH, 128>>>(h, t, lnout_g, lnout_b, DMODEL, 0);

    // [19] zz = gelu(t @ wh1 + bh1), batched over heads
    gemm_big<F_GELU><<<dim3(HD / BN, MG, NH), blk, SMB_BIG>>>(
        t, DMODEL, 0, wp_h1, HD, (long)DMODEL * HD, zz, NH * HD, HD,
        DMODEL, bh1, HD, nullptr, nullptr);

    // [20] zz = ln_head(zz), per-head params, in place
    ln_kernel<<<BATCH * NH, 128>>>(zz, zz, lnh_g, lnh_b, HD, NH);

    // [21] out = zz @ wh2 + bh2, batched over heads
    gemm_sm<0><<<dim3(OUTD / SBN, MG, NH), blk, SMB_SM>>>(
        zz, NH * HD, HD, wp_h2, OUTD, (long)HD * OUTD, out, NH * OUTD, OUTD,
        HD, bh2, OUTD);
}

// round 8
// speedup vs baseline: 1.0659x; 1.0659x over previous
#include <cuda_runtime.h>
#include <math.h>
#include <stdint.h>

// ---------------------------------------------------------------------------
// Shapes
// ---------------------------------------------------------------------------
#define BATCH  8192
#define DIN    4096
#define DMODEL 512
#define FDIM   2048
#define NH     3
#define HD     256
#define OUTD   896

// big GEMM tile (128x256, 8 warps of 64x64), 3-stage pipeline, 1 CTA/SM
#define BM 128
#define BN 256
#define BK 32
#define THREADS 256
#define AST 36
#define A_STAGE (BM * AST)                 // 4608 floats
#define B_STAGE (4 * BN * 8)               // 8192 floats  [g][n][8]
#define STAGE (A_STAGE + B_STAGE)          // 12800 floats
#define SMB_BIG (3 * STAGE * 4)            // 153600 B

// small GEMM tile (128x128, 8 warps of 32x64), 2-stage, 2 CTA/SM
#define SBN 128
#define SB_STAGE (4 * SBN * 8)             // 4096 floats
#define SSTAGE (A_STAGE + SB_STAGE)        // 8704 floats
#define SMB_SM (2 * SSTAGE * 4)            // 69632 B

// Epilogue flags
#define F_B2   1
#define F_GELU 2
#define F_RES  4

// ---------------------------------------------------------------------------
// Scratch
// ---------------------------------------------------------------------------
__device__ float g_h  [BATCH * DMODEL];
__device__ float g_t  [BATCH * DMODEL];
__device__ float g_cat[BATCH * 2 * DMODEL];
__device__ float g_ff [BATCH * FDIM];
__device__ float g_z  [BATCH * NH * HD];

// tf32-rounded, pair-packed weights: [K/8][N][8], pairs (k,k+4) adjacent
__device__ float g_wp_in [DIN * DMODEL];
__device__ float g_wp_osa[DMODEL * DMODEL];
__device__ float g_wp_oca[DMODEL * DMODEL];
__device__ float g_wp_stk[2 * DMODEL * DMODEL];   // stacked [Wsc ; Wcc], K=1024
__device__ float g_wp_ff1[DMODEL * FDIM];
__device__ float g_wp_ff2[FDIM * DMODEL];
__device__ float g_wp_h1 [NH * DMODEL * HD];
__device__ float g_wp_h2 [NH * HD * OUTD];

__device__ float g_tmp1[DMODEL * DMODEL];
__device__ float g_tmp2[DMODEL * DMODEL];
__device__ float g_bstk[DMODEL];
__device__ float g_zero[1024];

// ---------------------------------------------------------------------------
// Helpers
// ---------------------------------------------------------------------------
static __device__ __forceinline__ void cp16(float* sm, const float* gm) {
    unsigned s = (unsigned)__cvta_generic_to_shared(sm);
    asm volatile("cp.async.ca.shared.global [%0], [%1], 16;\n" :: "r"(s), "l"(gm));
}
static __device__ __forceinline__ unsigned f2tf32(float f) {
    unsigned u;
    asm("cvt.rna.tf32.f32 %0, %1;" : "=r"(u) : "f"(f));
    return u;
}
static __device__ __forceinline__ float gelu_exact(float v) {
    return 0.5f * v * (1.0f + erff(v * 0.70710678118654752f));
}
#define MMA_TF32(acc, a0, a1, a2, a3, b0, b1)                                  \
    asm volatile(                                                              \
        "mma.sync.aligned.m16n8k8.row.col.f32.tf32.tf32.f32 "                  \
        "{%0,%1,%2,%3},{%4,%5,%6,%7},{%8,%9},{%0,%1,%2,%3};\n"                 \
        : "+f"((acc)[0]), "+f"((acc)[1]), "+f"((acc)[2]), "+f"((acc)[3])       \
        : "r"(a0), "r"(a1), "r"(a2), "r"(a3), "r"(b0), "r"(b1))

// ---------------------------------------------------------------------------
// BIG: 128x256 CTA tile, 8 warps (2 M x 4 N) of 64x64, 3-stage pipeline.
// ---------------------------------------------------------------------------
template<int FLAGS>
__global__ void __launch_bounds__(THREADS, 1) gemm_big(
    const float* __restrict__ A, int lda, long sA,
    const float* __restrict__ B, int ldbN, long sB,
    float* __restrict__ C, int ldc, long sC,
    int K,
    const float* __restrict__ bias, int sBias,
    const float* __restrict__ bias2,
    const float* __restrict__ res)
{
    extern __shared__ float sm[];
    const int tid  = threadIdx.x;
    const int lane = tid & 31;
    const int warp = tid >> 5;
    const int wm = warp & 1;
    const int wn = warp >> 1;
    const int q  = lane >> 2, cc = lane & 3;

    const int z = blockIdx.z;
    A    += (long)z * sA;
    B    += (long)z * sB;
    C    += (long)z * sC;
    bias += (long)z * sBias;
    const float* resb = (FLAGS & F_RES) ? (res + (long)z * sC) : nullptr;

    const long mBase = (long)blockIdx.y * BM;
    const int  nBase = blockIdx.x * BN;
    const float* Ag = A + mBase * lda;

    const int numK = K / BK;

    float4 fA[4];
    auto ldgA = [&](int kt) {
#pragma unroll
        for (int i = 0; i < 4; i++) {
            int f = i * THREADS + tid;
            int r = f >> 3, c = (f & 7) * 4;
            fA[i] = *(const float4*)(Ag + (long)r * lda + kt * BK + c);
        }
    };
    auto stsA = [&](int stg) {
        float* As = sm + stg * STAGE;
#pragma unroll
        for (int i = 0; i < 4; i++) {
            int f = i * THREADS + tid;
            int r = f >> 3, c = (f & 7) * 4;
            float4 v = fA[i];
            *(uint4*)(As + r * AST + c) =
                make_uint4(f2tf32(v.x), f2tf32(v.y), f2tf32(v.z), f2tf32(v.w));
        }
    };
    auto cpB = [&](int kt, int stg) {
        float* Bs = sm + stg * STAGE + A_STAGE;
#pragma unroll
        for (int i = 0; i < 8; i++) {
            int idx = i * THREADS + tid;
            int half = idx & 1;
            int n = (idx >> 1) & 255;
            int g = idx >> 9;
            const float* src = B + ((long)(kt * 4 + g) * ldbN + nBase + n) * 8 + half * 4;
            cp16(Bs + (g * BN + n) * 8 + half * 4, src);
        }
    };

    float acc[4][8][4];
#pragma unroll
    for (int a = 0; a < 4; a++)
#pragma unroll
        for (int b = 0; b < 8; b++)
#pragma unroll
            for (int c = 0; c < 4; c++) acc[a][b][c] = 0.f;

    // ---- prologue ----
    ldgA(0); stsA(0);
    cpB(0, 0);
    asm volatile("cp.async.commit_group;\n" ::: "memory");
    ldgA(1);
    cpB(1, 1);
    asm volatile("cp.async.commit_group;\n" ::: "memory");

    for (int kt = 0; kt < numK; kt++) {
        asm volatile("cp.async.wait_group 1;\n" ::: "memory");
        __syncthreads();

        if (kt + 1 < numK) stsA((kt + 1) % 3);
        if (kt + 2 < numK) { ldgA(kt + 2); cpB(kt + 2, (kt + 2) % 3); }
        asm volatile("cp.async.commit_group;\n" ::: "memory");

        const float* As = sm + (kt % 3) * STAGE + (wm * 64) * AST;
        const float* Bs = sm + (kt % 3) * STAGE + A_STAGE;

#pragma unroll
        for (int ks = 0; ks < 4; ks++) {
            uint32_t af[4][4];
#pragma unroll
            for (int mi = 0; mi < 4; mi++) {
                const float* ap = As + (mi * 16 + q) * AST + ks * 8 + cc;
                af[mi][0] = __float_as_uint(ap[0]);
                af[mi][1] = __float_as_uint(ap[8 * AST]);
                af[mi][2] = __float_as_uint(ap[4]);
                af[mi][3] = __float_as_uint(ap[8 * AST + 4]);
            }
            uint32_t bf[8][2];
#pragma unroll
            for (int ni = 0; ni < 8; ni++) {
                uint2 bv = *(const uint2*)(Bs + ((ks * BN + wn * 64 + ni * 8 + q) * 8 + cc * 2));
                bf[ni][0] = bv.x; bf[ni][1] = bv.y;
            }
#pragma unroll
            for (int mi = 0; mi < 4; mi++)
#pragma unroll
                for (int ni = 0; ni < 8; ni++)
                    MMA_TF32(acc[mi][ni], af[mi][0], af[mi][1], af[mi][2], af[mi][3],
                             bf[ni][0], bf[ni][1]);
        }
    }

    // ---- fused epilogue ----
    const int rBase = (int)mBase + wm * 64;
    const int cBase = nBase + wn * 64;
#pragma unroll
    for (int mi = 0; mi < 4; mi++) {
#pragma unroll
        for (int ni = 0; ni < 8; ni++) {
            int c = cBase + ni * 8 + cc * 2;
            float b0 = bias[c], b1 = bias[c + 1];
            if (FLAGS & F_B2) { b0 += bias2[c]; b1 += bias2[c + 1]; }
#pragma unroll
            for (int h = 0; h < 2; h++) {
                long row = rBase + mi * 16 + q + 8 * h;
                float v0 = acc[mi][ni][2 * h + 0] + b0;
                float v1 = acc[mi][ni][2 * h + 1] + b1;
                if (FLAGS & F_GELU) { v0 = gelu_exact(v0); v1 = gelu_exact(v1); }
                long idx = row * ldc + c;
                if (FLAGS & F_RES) {
                    float2 rr = *(const float2*)(resb + idx);
                    v0 += rr.x; v1 += rr.y;
                }
                *(float2*)(C + idx) = make_float2(v0, v1);
            }
        }
    }
}

// ---------------------------------------------------------------------------
// SMALL: 128x128 CTA tile, 8 warps (4 M x 2 N) of 32x64, 2-stage, 2 CTA/SM.
// ---------------------------------------------------------------------------
template<int FLAGS>
__global__ void __launch_bounds__(THREADS, 2) gemm_sm(
    const float* __restrict__ A, int lda, long sA,
    const float* __restrict__ B, int ldbN, long sB,
    float* __restrict__ C, int ldc, long sC,
    int K,
    const float* __restrict__ bias, int sBias)
{
    extern __shared__ float sm[];
    const int tid  = threadIdx.x;
    const int lane = tid & 31;
    const int warp = tid >> 5;
    const int wm = warp & 3;
    const int wn = warp >> 2;
    const int q  = lane >> 2, cc = lane & 3;

    const int z = blockIdx.z;
    A    += (long)z * sA;
    B    += (long)z * sB;
    C    += (long)z * sC;
    bias += (long)z * sBias;

    const long mBase = (long)blockIdx.y * BM;
    const int  nBase = blockIdx.x * SBN;
    const float* Ag = A + mBase * lda;

    const int numK = K / BK;

    float4 fA[4];
    auto ldgA = [&](int kt) {
#pragma unroll
        for (int i = 0; i < 4; i++) {
            int f = i * THREADS + tid;
            int r = f >> 3, c = (f & 7) * 4;
            fA[i] = *(const float4*)(Ag + (long)r * lda + kt * BK + c);
        }
    };
    auto stsA = [&](int buf) {
        float* As = sm + buf * SSTAGE;
#pragma unroll
        for (int i = 0; i < 4; i++) {
            int f = i * THREADS + tid;
            int r = f >> 3, c = (f & 7) * 4;
            float4 v = fA[i];
            *(uint4*)(As + r * AST + c) =
                make_uint4(f2tf32(v.x), f2tf32(v.y), f2tf32(v.z), f2tf32(v.w));
        }
    };
    auto cpB = [&](int kt, int buf) {
        float* Bs = sm + buf * SSTAGE + A_STAGE;
#pragma unroll
        for (int i = 0; i < 4; i++) {
            int idx = i * THREADS + tid;
            int half = idx & 1;
            int n = (idx >> 1) & 127;
            int g = idx >> 8;
            const float* src = B + ((long)(kt * 4 + g) * ldbN + nBase + n) * 8 + half * 4;
            cp16(Bs + (g * SBN + n) * 8 + half * 4, src);
        }
    };

    float acc[2][8][4];
#pragma unroll
    for (int a = 0; a < 2; a++)
#pragma unroll
        for (int b = 0; b < 8; b++)
#pragma unroll
            for (int c = 0; c < 4; c++) acc[a][b][c] = 0.f;

    ldgA(0); stsA(0); cpB(0, 0);
    asm volatile("cp.async.commit_group;\n" ::: "memory");

    for (int kt = 0; kt < numK; kt++) {
        asm volatile("cp.async.wait_group 0;\n" ::: "memory");
        __syncthreads();

        if (kt + 1 < numK) {
            ldgA(kt + 1);
            cpB(kt + 1, (kt + 1) & 1);
            asm volatile("cp.async.commit_group;\n" ::: "memory");
        }

        const float* As = sm + (kt & 1) * SSTAGE + (wm * 32) * AST;
        const float* Bs = sm + (kt & 1) * SSTAGE + A_STAGE;

#pragma unroll
        for (int ks = 0; ks < 4; ks++) {
            uint32_t af[2][4];
#pragma unroll
            for (int mi = 0; mi < 2; mi++) {
                const float* ap = As + (mi * 16 + q) * AST + ks * 8 + cc;
                af[mi][0] = __float_as_uint(ap[0]);
                af[mi][1] = __float_as_uint(ap[8 * AST]);
                af[mi][2] = __float_as_uint(ap[4]);
                af[mi][3] = __float_as_uint(ap[8 * AST + 4]);
            }
            uint32_t bf[8][2];
#pragma unroll
            for (int ni = 0; ni < 8; ni++) {
                uint2 bv = *(const uint2*)(Bs + ((ks * SBN + wn * 64 + ni * 8 + q) * 8 + cc * 2));
                bf[ni][0] = bv.x; bf[ni][1] = bv.y;
            }
#pragma unroll
            for (int mi = 0; mi < 2; mi++)
#pragma unroll
                for (int ni = 0; ni < 8; ni++)
                    MMA_TF32(acc[mi][ni], af[mi][0], af[mi][1], af[mi][2], af[mi][3],
                             bf[ni][0], bf[ni][1]);
        }

        if (kt + 1 < numK) stsA((kt + 1) & 1);
    }

    const int rBase = (int)mBase + wm * 32;
    const int cBase = nBase + wn * 64;
#pragma unroll
    for (int mi = 0; mi < 2; mi++) {
#pragma unroll
        for (int ni = 0; ni < 8; ni++) {
            int c = cBase + ni * 8 + cc * 2;
            float b0 = bias[c], b1 = bias[c + 1];
#pragma unroll
            for (int h = 0; h < 2; h++) {
                long row = rBase + mi * 16 + q + 8 * h;
                float v0 = acc[mi][ni][2 * h + 0] + b0;
                float v1 = acc[mi][ni][2 * h + 1] + b1;
                if (FLAGS & F_GELU) { v0 = gelu_exact(v0); v1 = gelu_exact(v1); }
                long idx = row * ldc + c;
                *(float2*)(C + idx) = make_float2(v0, v1);
            }
        }
    }
}

// ---------------------------------------------------------------------------
// Weight pack: [K,N] fp32 -> [K/8][N][8] tf32, pair order {k0,k4,k1,k5,k2,k6,k3,k7}
// ---------------------------------------------------------------------------
__global__ void pack_kernel(const float* __restrict__ in, float* __restrict__ out,
                            int K, int N)
{
    const long zo = (long)blockIdx.z * K * N;
    const int n = blockIdx.x * 128 + threadIdx.x;
    const int g = blockIdx.y;
    float v[8];
#pragma unroll
    for (int k = 0; k < 8; k++)
        v[k] = in[zo + (long)(g * 8 + k) * N + n];
    float* o = out + zo + ((long)g * N + n) * 8;
    *(uint4*)(o)     = make_uint4(f2tf32(v[0]), f2tf32(v[4]), f2tf32(v[1]), f2tf32(v[5]));
    *(uint4*)(o + 4) = make_uint4(f2tf32(v[2]), f2tf32(v[6]), f2tf32(v[3]), f2tf32(v[7]));
}

// ---------------------------------------------------------------------------
// bias_init: bstk[n] = bo_sa[n] + bo_ca[n]; zero-init fold bias. grid 4 x 128.
// ---------------------------------------------------------------------------
__global__ void bias_init(const float* __restrict__ bo_sa, const float* __restrict__ bo_ca,
                          float* __restrict__ bstk, float* __restrict__ zero)
{
    const int n = blockIdx.x * 128 + threadIdx.x;
    zero[n] = 0.f;
    zero[n + 512] = 0.f;
    bstk[n] = bo_sa[n] + bo_ca[n];
}

// ---------------------------------------------------------------------------
// bias_fold: bstk[n] += sum_k bvsa[k]Wosa[k,n] + bvca[k]Woca[k,n]
// grid (4, 8) x 128 threads: 8-way k-parallel, coalesced over n, one
// atomicAdd per thread. Replaces the 140us serial prep_bias.
// ---------------------------------------------------------------------------
__global__ void bias_fold(const float* __restrict__ bv_sa, const float* __restrict__ wo_sa,
                          const float* __restrict__ bv_ca, const float* __restrict__ wo_ca,
                          float* __restrict__ bstk)
{
    const int n  = blockIdx.x * 128 + threadIdx.x;
    const int k0 = blockIdx.y * 64;
    float a0 = 0.f, a1 = 0.f;
#pragma unroll 8
    for (int k = 0; k < 64; k += 2) {
        a0 += bv_sa[k0 + k]     * wo_sa[(long)(k0 + k) * DMODEL + n]
            + bv_ca[k0 + k]     * wo_ca[(long)(k0 + k) * DMODEL + n];
        a1 += bv_sa[k0 + k + 1] * wo_sa[(long)(k0 + k + 1) * DMODEL + n]
            + bv_ca[k0 + k + 1] * wo_ca[(long)(k0 + k + 1) * DMODEL + n];
    }
    atomicAdd(bstk + n, a0 + a1);
}

// ---------------------------------------------------------------------------
// Row LayerNorm (float4, 128 threads)
// ---------------------------------------------------------------------------
__global__ void ln_kernel(const float* __restrict__ in, float* __restrict__ out,
                          const float* __restrict__ g, const float* __restrict__ b,
                          int C, int headMod)
{
    __shared__ float red[8];
    const int row = blockIdx.x;
    const float* x = in + (long)row * C;
    float* y = out + (long)row * C;
    const int go = headMod ? (row % headMod) * C : 0;

    float s = 0.f, s2 = 0.f;
    for (int i = threadIdx.x * 4; i < C; i += 512) {
        float4 v = *(const float4*)(x + i);
        s  += v.x + v.y + v.z + v.w;
        s2 += v.x * v.x + v.y * v.y + v.z * v.z + v.w * v.w;
    }
#pragma unroll
    for (int o = 16; o; o >>= 1) {
        s  += __shfl_xor_sync(0xffffffffu, s, o);
        s2 += __shfl_xor_sync(0xffffffffu, s2, o);
    }
    const int w = threadIdx.x >> 5;
    if ((threadIdx.x & 31) == 0) { red[w] = s; red[4 + w] = s2; }
    __syncthreads();
    if (threadIdx.x == 0) {
        float ts = 0.f, ts2 = 0.f;
#pragma unroll
        for (int i = 0; i < 4; i++) { ts += red[i]; ts2 += red[4 + i]; }
        red[0] = ts; red[4] = ts2;
    }
    __syncthreads();
    const float mean = red[0] / C;
    const float var  = red[4] / C - mean * mean;
    const float inv  = rsqrtf(var + 1e-5f);
    for (int i = threadIdx.x * 4; i < C; i += 512) {
        float4 v  = *(const float4*)(x + i);
        float4 gg = *(const float4*)(g + go + i);
        float4 bb = *(const float4*)(b + go + i);
        float4 o;
        o.x = (v.x - mean) * inv * gg.x + bb.x;
        o.y = (v.y - mean) * inv * gg.y + bb.y;
        o.z = (v.z - mean) * inv * gg.z + bb.z;
        o.w = (v.w - mean) * inv * gg.w + bb.w;
        *(float4*)(y + i) = o;
    }
}

// ---------------------------------------------------------------------------
// lncat: cat[row, 0:512] = ln1(h[row]); cat[row, 512:1024] = h[row]
// ---------------------------------------------------------------------------
__global__ void lncat_kernel(const float* __restrict__ in, float* __restrict__ cat,
                             const float* __restrict__ g, const float* __restrict__ b)
{
    __shared__ float red[8];
    const int row = blockIdx.x;
    const float* x = in + (long)row * DMODEL;
    float* y = cat + (long)row * (2 * DMODEL);
    const int i = threadIdx.x * 4;

    float4 v = *(const float4*)(x + i);
    float s  = v.x + v.y + v.z + v.w;
    float s2 = v.x * v.x + v.y * v.y + v.z * v.z + v.w * v.w;
#pragma unroll
    for (int o = 16; o; o >>= 1) {
        s  += __shfl_xor_sync(0xffffffffu, s, o);
        s2 += __shfl_xor_sync(0xffffffffu, s2, o);
    }
    const int w = threadIdx.x >> 5;
    if ((threadIdx.x & 31) == 0) { red[w] = s; red[4 + w] = s2; }
    __syncthreads();
    if (threadIdx.x == 0) {
        float ts = 0.f, ts2 = 0.f;
#pragma unroll
        for (int j = 0; j < 4; j++) { ts += red[j]; ts2 += red[4 + j]; }
        red[0] = ts; red[4] = ts2;
    }
    __syncthreads();
    const float mean = red[0] / DMODEL;
    const float var  = red[4] / DMODEL - mean * mean;
    const float inv  = rsqrtf(var + 1e-5f);
    float4 gg = *(const float4*)(g + i);
    float4 bb = *(const float4*)(b + i);
    float4 o;
    o.x = (v.x - mean) * inv * gg.x + bb.x;
    o.y = (v.y - mean) * inv * gg.y + bb.y;
    o.z = (v.z - mean) * inv * gg.z + bb.z;
    o.w = (v.w - mean) * inv * gg.w + bb.w;
    *(float4*)(y + i) = o;
    *(float4*)(y + DMODEL + i) = v;
}

// ---------------------------------------------------------------------------
// Launch
// ---------------------------------------------------------------------------
extern "C" void kernel_launch(void* const* d_in, const int* in_sizes, int n_in,
                              void* d_out, int out_size)
{
    const float* x      = (const float*)d_in[0];
    const float* w_in   = (const float*)d_in[1];
    const float* b_in   = (const float*)d_in[2];
    const float* pos    = (const float*)d_in[3];
    const float* ln1_g  = (const float*)d_in[4];
    const float* ln1_b  = (const float*)d_in[5];
    const float* wv_sa  = (const float*)d_in[6];
    const float* bv_sa  = (const float*)d_in[7];
    const float* wo_sa  = (const float*)d_in[8];
    const float* bo_sa  = (const float*)d_in[9];
    const float* wv_ca  = (const float*)d_in[12];
    const float* bv_ca  = (const float*)d_in[13];
    const float* wo_ca  = (const float*)d_in[14];
    const float* bo_ca  = (const float*)d_in[15];
    const float* ln3_g  = (const float*)d_in[16];
    const float* ln3_b  = (const float*)d_in[17];
    const float* w_ff1  = (const float*)d_in[18];
    const float* b_ff1  = (const float*)d_in[19];
    const float* w_ff2  = (const float*)d_in[20];
    const float* b_ff2  = (const float*)d_in[21];
    const float* lnout_g= (const float*)d_in[22];
    const float* lnout_b= (const float*)d_in[23];
    const float* wh1    = (const float*)d_in[24];
    const float* bh1    = (const float*)d_in[25];
    const float* lnh_g  = (const float*)d_in[26];
    const float* lnh_b  = (const float*)d_in[27];
    const float* wh2    = (const float*)d_in[28];
    const float* bh2    = (const float*)d_in[29];
    float* out = (float*)d_out;

    float *h, *t, *cat, *ff, *zz, *tmp1, *tmp2, *bstk, *zero;
    float *wp_in, *wp_osa, *wp_oca, *wp_stk, *wp_ff1, *wp_ff2, *wp_h1, *wp_h2;
    cudaGetSymbolAddress((void**)&h,    g_h);
    cudaGetSymbolAddress((void**)&t,    g_t);
    cudaGetSymbolAddress((void**)&cat,  g_cat);
    cudaGetSymbolAddress((void**)&ff,   g_ff);
    cudaGetSymbolAddress((void**)&zz,   g_z);
    cudaGetSymbolAddress((void**)&tmp1, g_tmp1);
    cudaGetSymbolAddress((void**)&tmp2, g_tmp2);
    cudaGetSymbolAddress((void**)&bstk, g_bstk);
    cudaGetSymbolAddress((void**)&zero, g_zero);
    cudaGetSymbolAddress((void**)&wp_in,  g_wp_in);
    cudaGetSymbolAddress((void**)&wp_osa, g_wp_osa);
    cudaGetSymbolAddress((void**)&wp_oca, g_wp_oca);
    cudaGetSymbolAddress((void**)&wp_stk, g_wp_stk);
    cudaGetSymbolAddress((void**)&wp_ff1, g_wp_ff1);
    cudaGetSymbolAddress((void**)&wp_ff2, g_wp_ff2);
    cudaGetSymbolAddress((void**)&wp_h1,  g_wp_h1);
    cudaGetSymbolAddress((void**)&wp_h2,  g_wp_h2);

    cudaFuncSetAttribute(gemm_big<F_B2>,   cudaFuncAttributeMaxDynamicSharedMemorySize, SMB_BIG);
    cudaFuncSetAttribute(gemm_big<F_RES>,  cudaFuncAttributeMaxDynamicSharedMemorySize, SMB_BIG);
    cudaFuncSetAttribute(gemm_big<F_GELU>, cudaFuncAttributeMaxDynamicSharedMemorySize, SMB_BIG);
    cudaFuncSetAttribute(gemm_sm<0>,       cudaFuncAttributeMaxDynamicSharedMemorySize, SMB_SM);

    dim3 blk(THREADS);
    const int MG = BATCH / BM;  // 64

    // ---- launch order: index 5 = gemm1 (ncu -s 5 -c 1 profiles it) ----
    // [0] pack w_in
    pack_kernel<<<dim3(DMODEL / 128, DIN / 8, 1), 128>>>(w_in, wp_in, DIN, DMODEL);
    // [1] pack wo_sa
    pack_kernel<<<dim3(DMODEL / 128, DMODEL / 8, 1), 128>>>(wo_sa, wp_osa, DMODEL, DMODEL);
    // [2] pack wo_ca
    pack_kernel<<<dim3(DMODEL / 128, DMODEL / 8, 1), 128>>>(wo_ca, wp_oca, DMODEL, DMODEL);
    // [3] bias init (+zero init for fold GEMMs)
    bias_init<<<4, 128>>>(bo_sa, bo_ca, bstk, zero);
    // [4] bias fold (parallel, atomic)
    bias_fold<<<dim3(4, 8), 128>>>(bv_sa, wo_sa, bv_ca, wo_ca, bstk);
    // [5] gemm1: h = x @ w_in + b_in + pos          <-- PROFILED LAUNCH
    gemm_big<F_B2><<<dim3(DMODEL / BN, MG, 1), blk, SMB_BIG>>>(
        x, DIN, 0, wp_in, DMODEL, 0, h, DMODEL, 0, DIN, b_in, 0, pos, nullptr);
    // [6] fold1: tmp1 = Wvsa @ Wosa
    gemm_sm<0><<<dim3(DMODEL / SBN, DMODEL / BM, 1), blk, SMB_SM>>>(
        wv_sa, DMODEL, 0, wp_osa, DMODEL, 0, tmp1, DMODEL, 0, DMODEL, zero, 0);
    // [7] fold2: tmp2 = Wvca @ Woca
    gemm_sm<0><<<dim3(DMODEL / SBN, DMODEL / BM, 1), blk, SMB_SM>>>(
        wv_ca, DMODEL, 0, wp_oca, DMODEL, 0, tmp2, DMODEL, 0, DMODEL, zero, 0);
    // [8,9] stack folds into wp_stk (packed K=1024)
    pack_kernel<<<dim3(DMODEL / 128, DMODEL / 8, 1), 128>>>(tmp1, wp_stk, DMODEL, DMODEL);
    pack_kernel<<<dim3(DMODEL / 128, DMODEL / 8, 1), 128>>>(
        tmp2, wp_stk + (DMODEL / 8) * DMODEL * 8, DMODEL, DMODEL);
    // [10..13] remaining weight packs
    pack_kernel<<<dim3(FDIM / 128, DMODEL / 8, 1), 128>>>(w_ff1, wp_ff1, DMODEL, FDIM);
    pack_kernel<<<dim3(DMODEL / 128, FDIM / 8, 1), 128>>>(w_ff2, wp_ff2, FDIM, DMODEL);
    pack_kernel<<<dim3(HD / 128, DMODEL / 8, NH), 128>>>(wh1, wp_h1, DMODEL, HD);
    pack_kernel<<<dim3(OUTD / 128, HD / 8, NH), 128>>>(wh2, wp_h2, HD, OUTD);

    // [14] cat = [ln1(h) | h]
    lncat_kernel<<<BATCH, 128>>>(h, cat, ln1_g, ln1_b);

    // [15] h = h + cat @ Wstk + bstk     (folded self-attn + cross-attn, K=1024)
    gemm_big<F_RES><<<dim3(DMODEL / BN, MG, 1), blk, SMB_BIG>>>(
        cat, 2 * DMODEL, 0, wp_stk, DMODEL, 0, h, DMODEL, 0, 2 * DMODEL,
        bstk, 0, nullptr, h);

    // [16] t = ln3(h)
    ln_kernel<<<BATCH, 128>>>(h, t, ln3_g, ln3_b, DMODEL, 0);

    // [17] ff = gelu(t @ w_ff1 + b_ff1)
    gemm_big<F_GELU><<<dim3(FDIM / BN, MG, 1), blk, SMB_BIG>>>(
        t, DMODEL, 0, wp_ff1, FDIM, 0, ff, FDIM, 0, DMODEL, b_ff1, 0, nullptr, nullptr);

    // [18] h = h + ff @ w_ff2 + b_ff2   (in place)
    gemm_big<F_RES><<<dim3(DMODEL / BN, MG, 1), blk, SMB_BIG>>>(
        ff, FDIM, 0, wp_ff2, DMODEL, 0, h, DMODEL, 0, FDIM, b_ff2, 0, nullptr, h);

    // [19] t = lnout(h)
    ln_kernel<<<BATCH, 128>>>(h, t, lnout_g, lnout_b, DMODEL, 0);

    // [20] zz = gelu(t @ wh1 + bh1), batched over heads
    gemm_big<F_GELU><<<dim3(HD / BN, MG, NH), blk, SMB_BIG>>>(
        t, DMODEL, 0, wp_h1, HD, (long)DMODEL * HD, zz, NH * HD, HD,
        DMODEL, bh1, HD, nullptr, nullptr);

    // [21] zz = ln_head(zz), per-head params, in place
    ln_kernel<<<BATCH * NH, 128>>>(zz, zz, lnh_g, lnh_b, HD, NH);

    // [22] out = zz @ wh2 + bh2, batched over heads
    gemm_sm<0><<<dim3(OUTD / SBN, MG, NH), blk, SMB_SM>>>(
        zz, NH * HD, HD, wp_h2, OUTD, (long)HD * OUTD, out, NH * OUTD, OUTD,
        HD, bh2, OUTD);
}